// round 11
// baseline (speedup 1.0000x reference)
#include <cuda_runtime.h>
#include <cuda_bf16.h>
#include <math.h>
#include <stdint.h>

#define B_   16
#define N_   1024
#define C2_  64
#define D_   32
#define H_   64
#define NC_  10
#define EPSF 1e-11f

__device__ float g_u[B_ * H_];
__device__ float g_S[B_];
__device__ float g_c[B_];

__device__ __forceinline__ uint32_t smem_u32(const void* p) {
    uint32_t a;
    asm("{ .reg .u64 t; cvta.to.shared.u64 t, %1; cvt.u32.u64 %0, t; }"
        : "=r"(a) : "l"(p));
    return a;
}
#define SWZ(off) ((off) ^ (((off) >> 3) & 0x70))

__device__ __forceinline__ void ldm_x4(uint32_t* r, uint32_t addr) {
    asm volatile("ldmatrix.sync.aligned.m8n8.x4.shared.b16 {%0,%1,%2,%3}, [%4];"
        : "=r"(r[0]), "=r"(r[1]), "=r"(r[2]), "=r"(r[3]) : "r"(addr));
}
__device__ __forceinline__ void mma_bf16(float* c, const uint32_t* a,
                                         uint32_t b0, uint32_t b1) {
    asm volatile(
        "mma.sync.aligned.m16n8k16.row.col.f32.bf16.bf16.f32 "
        "{%0,%1,%2,%3}, {%4,%5,%6,%7}, {%8,%9}, {%0,%1,%2,%3};"
        : "+f"(c[0]), "+f"(c[1]), "+f"(c[2]), "+f"(c[3])
        : "r"(a[0]), "r"(a[1]), "r"(a[2]), "r"(a[3]), "r"(b0), "r"(b1));
}

// ---------------------------------------------------------------------------
// Kernel 1: per-batch prep -> g_u / g_S / g_c
// ---------------------------------------------------------------------------
__global__ __launch_bounds__(256) void prep_kernel(
    const float* __restrict__ second, const float* __restrict__ classc,
    const int* __restrict__ y, const float* __restrict__ W1,
    const float* __restrict__ b1)
{
    int b = blockIdx.x;
    int t = threadIdx.x;

    __shared__ float s_W1[H_ * D_];
    __shared__ float s_sn[C2_];
    __shared__ float s_scu[C2_][D_];
    __shared__ float s_secin[9][D_];
    __shared__ float s_scale[9];
    __shared__ float s_sec[9][H_];
    __shared__ float s_red[H_];

    #pragma unroll
    for (int i = 0; i < 2; i++)
        ((float4*)s_W1)[t + i * 256] = ((const float4*)W1)[t + i * 256];

    if (t < C2_) {
        const float* p = second + (b * C2_ + t) * D_;
        float sn = 0.f;
        #pragma unroll
        for (int d = 0; d < D_; d++) { float x = p[d]; sn += x * x; }
        s_sn[t] = sn;
        float inv = 1.0f / sqrtf(sn + EPSF);
        #pragma unroll
        for (int d = 0; d < D_; d++) s_scu[t][d] = p[d] * inv;
    }
    __syncthreads();

    if (t < C2_) {
        float mysn = s_sn[t];
        int rank = 0;
        #pragma unroll
        for (int c = 0; c < C2_; c++) {
            float o = s_sn[c];
            rank += (o > mysn) || (o == mysn && c < t);
        }
        if (rank < 8) {
            s_scale[rank] = mysn / (1.f + mysn);
            #pragma unroll
            for (int d = 0; d < D_; d++) s_secin[rank][d] = s_scu[t][d];
        }
    } else if (t == C2_) {
        int yb = y[b];
        if ((unsigned)yb >= (unsigned)NC_) {
            float yf = __int_as_float(yb);
            yb = (int)yf;
            if ((unsigned)yb >= (unsigned)NC_) yb = 0;
        }
        const float* cp = classc + (b * NC_ + yb) * D_;
        float sn = 0.f;
        for (int d = 0; d < D_; d++) sn += cp[d] * cp[d];
        float inv = 1.f / sqrtf(sn + EPSF);
        for (int d = 0; d < D_; d++) s_secin[8][d] = cp[d] * inv;
        s_scale[8] = sn / (1.f + sn);
    }
    __syncthreads();

    for (int o = t; o < 9 * H_; o += 256) {
        int k = o >> 6, h = o & 63;
        float acc = b1[h];
        #pragma unroll
        for (int d = 0; d < D_; d++) acc += s_secin[k][d] * s_W1[h * D_ + d];
        s_sec[k][h] = fmaxf(acc, 0.f);
    }
    __syncthreads();

    if (t < H_) {
        float uh = 0.f, ch = 0.f;
        #pragma unroll
        for (int k = 0; k < 9; k++) {
            float sk = s_scale[k], sv = s_sec[k][t];
            uh += sk * sv;
            ch += sk * sv * sv;
        }
        g_u[b * H_ + t] = uh;
        s_red[t] = ch;
    }
    __syncthreads();
    if (t < 32) {
        float r2 = s_red[t] + s_red[t + 32];
        #pragma unroll
        for (int o = 16; o; o >>= 1) r2 += __shfl_xor_sync(0xFFFFFFFFu, r2, o);
        if (t == 0) {
            float S = 0.f;
            #pragma unroll
            for (int k = 0; k < 9; k++) S += s_scale[k];
            g_S[b] = S;
            g_c[b] = r2;
        }
    }
}

// ---------------------------------------------------------------------------
// Kernel 2: symmetric Gram, mma.sync bf16 hi/lo, ONE sync.
//  - loads first_capsule fp32; relu + hi/lo split + v-reduction fused in load
//  - normal tile: direct fragment float2 stores
//  - transposed tile (off-diag): direct fragment scalar stores (32B segments)
// ---------------------------------------------------------------------------
#define SM_AHI   0
#define SM_ALO   16384
#define SM_BHI   32768
#define SM_BLO   49152
#define SM_VN    65536
#define SM_VM    66048
#define SM_MKN   66560
#define SM_MKM   67072
#define SM_TOTAL 67584

__global__ __launch_bounds__(256, 2) void gram_kernel(
    const float* __restrict__ first,
    const unsigned int* __restrict__ mask, float* __restrict__ out)
{
    extern __shared__ char smem[];
    uint32_t sb = smem_u32(smem);

    int rem = blockIdx.x, nt = 0;          // triangular decode, [0,36)
    while (rem >= 8 - nt) { rem -= 8 - nt; nt++; }
    int mt = nt + rem;
    int b = blockIdx.z;
    int t = threadIdx.x, w = t >> 5, l = t & 31;
    int n0 = nt * 128, m0 = mt * 128;
    bool offdiag = (nt != mt);

    // per-batch scalars + u chunk (thread's k-range = (t&7)*8 .. +7)
    float S  = __ldg(&g_S[b]);
    float cb = __ldg(&g_c[b]);
    float4 u0 = __ldg((const float4*)(g_u + b * H_ + (t & 7) * 8));
    float4 u1 = __ldg((const float4*)(g_u + b * H_ + (t & 7) * 8 + 4));
    float ur[8] = {u0.x, u0.y, u0.z, u0.w, u1.x, u1.y, u1.z, u1.w};

    // mask rows -> smem
    if (t < 128) ((unsigned int*)(smem + SM_MKN))[t] = mask[b * N_ + n0 + t];
    else         ((unsigned int*)(smem + SM_MKM))[t - 128] = mask[b * N_ + m0 + (t - 128)];

    // ---- tile load: relu + bf16 hi/lo split + fused v-reduction ----
    #pragma unroll
    for (int side = 0; side < 2; side++) {
        if (side == 1 && !offdiag) break;
        const float* src = first + ((size_t)(b * N_ + (side ? m0 : n0))) * H_;
        float* vdst = (float*)(smem + (side ? SM_VM : SM_VN));
        #pragma unroll
        for (int it = 0; it < 4; it++) {
            int flat = t + it * 256;           // 0..1023
            int r = flat >> 3, q = t & 7;      // row, 8-float chunk (q==flat&7)
            float4 a0 = ((const float4*)(src + r * H_ + q * 8))[0];
            float4 a1 = ((const float4*)(src + r * H_ + q * 8))[1];
            float x[8] = {fmaxf(a0.x,0.f), fmaxf(a0.y,0.f), fmaxf(a0.z,0.f), fmaxf(a0.w,0.f),
                          fmaxf(a1.x,0.f), fmaxf(a1.y,0.f), fmaxf(a1.z,0.f), fmaxf(a1.w,0.f)};
            // v partial: this thread's 8 k's, reduce across the 8 threads of row r
            float part = 0.f;
            #pragma unroll
            for (int k = 0; k < 8; k++) part = fmaf(x[k], ur[k], part);
            part += __shfl_xor_sync(0xFFFFFFFFu, part, 1);
            part += __shfl_xor_sync(0xFFFFFFFFu, part, 2);
            part += __shfl_xor_sync(0xFFFFFFFFu, part, 4);
            if (q == 0) vdst[r] = part;

            uint32_t hw[4], lw[4];
            #pragma unroll
            for (int p2 = 0; p2 < 4; p2++) {
                __nv_bfloat16 h0 = __float2bfloat16(x[2*p2]);
                __nv_bfloat16 h1 = __float2bfloat16(x[2*p2+1]);
                __nv_bfloat16 l0 = __float2bfloat16(x[2*p2]   - __bfloat162float(h0));
                __nv_bfloat16 l1 = __float2bfloat16(x[2*p2+1] - __bfloat162float(h1));
                hw[p2] = ((uint32_t)__bfloat16_as_ushort(h1) << 16) | __bfloat16_as_ushort(h0);
                lw[p2] = ((uint32_t)__bfloat16_as_ushort(l1) << 16) | __bfloat16_as_ushort(l0);
            }
            uint32_t off = SWZ((uint32_t)(r * 128 + q * 16));
            *(uint4*)(smem + (side ? SM_BHI : SM_AHI) + off) = make_uint4(hw[0], hw[1], hw[2], hw[3]);
            *(uint4*)(smem + (side ? SM_BLO : SM_ALO) + off) = make_uint4(lw[0], lw[1], lw[2], lw[3]);
        }
    }
    __syncthreads();     // the ONLY block-wide sync

    // ---- mma mainloop ----
    int rw = w & 3;        // n row-block (32 rows)
    int cw = w >> 2;       // m col-block (64 cols)
    int g = l >> 3, lr = l & 7;

    float acc[2][8][4];
    #pragma unroll
    for (int i = 0; i < 2; i++)
        #pragma unroll
        for (int j = 0; j < 8; j++)
            #pragma unroll
            for (int q = 0; q < 4; q++) acc[i][j][q] = 0.f;

    uint32_t baseA = sb + SM_AHI;
    uint32_t baseB = sb + (offdiag ? SM_BHI : SM_AHI);

    int arow = rw * 32 + (g & 1) * 8 + lr;
    int acol = (g >> 1) * 16;
    int brow = cw * 64 + (g >> 1) * 8 + lr;
    int bcol = (g & 1) * 16;

    #pragma unroll
    for (int ks = 0; ks < 4; ks++) {
        uint32_t ahi[2][4], alo[2][4];
        #pragma unroll
        for (int i = 0; i < 2; i++) {
            uint32_t byte = SWZ((uint32_t)((arow + i * 16) * 128 + ks * 32 + acol));
            ldm_x4(ahi[i], baseA + byte);
            ldm_x4(alo[i], baseA + 16384 + byte);
        }
        #pragma unroll
        for (int jp = 0; jp < 4; jp++) {
            uint32_t bhi[4], blo[4];
            uint32_t byte = SWZ((uint32_t)((brow + jp * 16) * 128 + ks * 32 + bcol));
            ldm_x4(bhi, baseB + byte);
            ldm_x4(blo, baseB + 16384 + byte);
            #pragma unroll
            for (int i = 0; i < 2; i++) {
                mma_bf16(acc[i][2 * jp],     ahi[i], bhi[0], bhi[1]);
                mma_bf16(acc[i][2 * jp + 1], ahi[i], bhi[2], bhi[3]);
                mma_bf16(acc[i][2 * jp],     alo[i], bhi[0], bhi[1]);
                mma_bf16(acc[i][2 * jp + 1], alo[i], bhi[2], bhi[3]);
                mma_bf16(acc[i][2 * jp],     ahi[i], blo[0], blo[1]);
                mma_bf16(acc[i][2 * jp + 1], ahi[i], blo[2], blo[3]);
            }
        }
    }

    const float* vn = (const float*)(smem + SM_VN);
    const float* vm = (const float*)(smem + (offdiag ? SM_VM : SM_VN));
    const unsigned int* mkN = (const unsigned int*)(smem + SM_MKN);
    const unsigned int* mkM = (const unsigned int*)(smem + (offdiag ? SM_MKM : SM_MKN));

    // ---- normal orientation: direct fragment float2 stores ----
    {
        int rbase = rw * 32 + (l >> 2);
        float base4[4]; bool mk4[4];
        #pragma unroll
        for (int ii = 0; ii < 4; ii++) {
            int r = rbase + ii * 8;
            mk4[ii]   = (mkN[r] != 0u);
            base4[ii] = vn[r] + cb;
        }
        int cg = cw * 64 + (l & 3) * 2;
        #pragma unroll
        for (int j = 0; j < 8; j++) {
            int c = cg + j * 8;
            float2 vm2 = *(const float2*)&vm[c];
            #pragma unroll
            for (int ii = 0; ii < 4; ii++) {
                int i = ii >> 1, qq = (ii & 1) * 2;
                float2 o;
                if (mk4[ii]) {
                    o.x = fmaf(S, acc[i][j][qq],     base4[ii] + vm2.x);
                    o.y = fmaf(S, acc[i][j][qq + 1], base4[ii] + vm2.y);
                } else { o = make_float2(0.f, 0.f); }
                int n = n0 + rbase + ii * 8;
                *(float2*)(out + ((size_t)(b * N_ + n)) * N_ + m0 + c) = o;
            }
        }
    }

    // ---- off-diagonal: direct transposed scalar stores ----
    if (offdiag) {
        int rr = rw * 32 + (l >> 2);
        float vnv[4] = {vn[rr] + 0.f, vn[rr + 8], vn[rr + 16], vn[rr + 24]};
        #pragma unroll
        for (int j = 0; j < 8; j++) {
            int cpair = cw * 64 + j * 8 + (l & 3) * 2;
            #pragma unroll
            for (int cc = 0; cc < 2; cc++) {
                int c = cpair + cc;
                bool mk = (mkM[c] != 0u);
                float bse = vm[c] + cb;
                float* op = out + ((size_t)(b * N_ + m0 + c)) * N_ + n0 + rr;
                if (mk) {
                    op[0]  = fmaf(S, acc[0][j][cc],     bse + vnv[0]);
                    op[8]  = fmaf(S, acc[0][j][cc + 2], bse + vnv[1]);
                    op[16] = fmaf(S, acc[1][j][cc],     bse + vnv[2]);
                    op[24] = fmaf(S, acc[1][j][cc + 2], bse + vnv[3]);
                } else {
                    op[0] = 0.f; op[8] = 0.f; op[16] = 0.f; op[24] = 0.f;
                }
            }
        }
    }
}

// ---------------------------------------------------------------------------
extern "C" void kernel_launch(void* const* d_in, const int* in_sizes, int n_in,
                              void* d_out, int out_size)
{
    const float* first  = nullptr;
    const float* second = nullptr;
    const float* classc = nullptr;
    const int*   y      = nullptr;
    const unsigned int* mask = nullptr;
    const float* W1     = nullptr;
    const float* b1     = nullptr;
    for (int i = 0; i < n_in; i++) {
        switch (in_sizes[i]) {
            case 1048576: first  = (const float*)d_in[i]; break;
            case 32768:   second = (const float*)d_in[i]; break;
            case 5120:    classc = (const float*)d_in[i]; break;
            case 16:      y      = (const int*)d_in[i]; break;
            case 16384:   mask   = (const unsigned int*)d_in[i]; break;
            case 2048:    W1     = (const float*)d_in[i]; break;
            case 64:      b1     = (const float*)d_in[i]; break;
            default: break;
        }
    }
    float* out = (float*)d_out;
    (void)out_size;

    prep_kernel<<<B_, 256>>>(second, classc, y, W1, b1);

    cudaFuncSetAttribute(gram_kernel,
                         cudaFuncAttributeMaxDynamicSharedMemorySize, SM_TOTAL);
    dim3 grid(36, 1, B_);
    gram_kernel<<<grid, 256, SM_TOTAL>>>(first, mask, out);
}